// round 1
// baseline (speedup 1.0000x reference)
#include <cuda_runtime.h>

// MedSegNet texture-feature kernel, algebraically simplified:
//   entropy  = -(1/9) * box9( g ),  g = cl*ln(cl), cl = max(p, 1e-6)
//              (zero-pad cells give g automatically from p=0)
//   energy   = (1/9) * box9( p^2 )
//   contrast = popvar / max(var_unbiased, 1e-6)       (std clamp folded; no sqrt)
//   homog    = 1 / (1 + (1/9)*box9(|p - mean|) + 1e-6)
//   M(f)     = clamp(max(f,1e-5) * exp(-0.5), 1e-4, 1e4)   (theta=1 folds log/exp away)

#define H 128
#define W 128
#define CIN 64
#define BATCH 8
#define TILE_H 16
#define SH (TILE_H + 2)
#define SW (W + 2)

__global__ __launch_bounds__(512, 4)
void medseg_kernel(const float* __restrict__ x, float* __restrict__ out) {
    // blockIdx.y = plane index bc in [0, B*C); blockIdx.x = row-tile in [0, H/TILE_H)
    const int bc = blockIdx.y;
    const int rowBase = blockIdx.x * TILE_H;

    __shared__ float sp[SH][SW];
    __shared__ float sg[SH][SW];

    const int tx = threadIdx.x;          // 0..127
    const int ty = threadIdx.y;          // 0..3
    const int tid = ty * 128 + tx;       // 0..511

    const float* __restrict__ plane = x + (size_t)bc * (H * W);

    // ---- cooperative load of tile + 1-halo; compute g = cl*ln(cl) once per cell ----
    #pragma unroll
    for (int i = tid; i < SH * SW; i += 512) {
        const int sr = i / SW;
        const int sc = i - sr * SW;
        const int gr = rowBase + sr - 1;
        const int gc = sc - 1;
        float p = 0.0f;
        if ((unsigned)gr < (unsigned)H && (unsigned)gc < (unsigned)W)
            p = plane[gr * W + gc];
        const float cl = fmaxf(p, 1e-6f);
        sp[sr][sc] = p;
        sg[sr][sc] = cl * __logf(cl);    // pad cell -> 1e-6*ln(1e-6) automatically
    }
    __syncthreads();

    const float INV9 = 1.0f / 9.0f;
    const float EMH  = 0.60653066f;      // exp(-0.5)

    float* __restrict__ outp = out + (size_t)(4 * bc) * (H * W);

    #pragma unroll
    for (int k = 0; k < TILE_H / 4; k++) {
        const int lr = ty + k * 4;       // local row 0..15
        const int sr = lr + 1;
        const int sc = tx + 1;

        // gather 9 values, keep in registers
        float p0 = sp[sr-1][sc-1], p1 = sp[sr-1][sc], p2 = sp[sr-1][sc+1];
        float p3 = sp[sr  ][sc-1], p4 = sp[sr  ][sc], p5 = sp[sr  ][sc+1];
        float p6 = sp[sr+1][sc-1], p7 = sp[sr+1][sc], p8 = sp[sr+1][sc+1];

        float S  = ((p0 + p1) + (p2 + p3)) + ((p4 + p5) + (p6 + p7)) + p8;
        float P2 = p0*p0 + p1*p1 + p2*p2 + p3*p3 + p4*p4
                 + p5*p5 + p6*p6 + p7*p7 + p8*p8;
        float G  = ((sg[sr-1][sc-1] + sg[sr-1][sc]) + (sg[sr-1][sc+1] + sg[sr][sc-1]))
                 + ((sg[sr][sc] + sg[sr][sc+1]) + (sg[sr+1][sc-1] + sg[sr+1][sc]))
                 + sg[sr+1][sc+1];

        const float mean = S * INV9;

        // centered pass (numerically matches reference's (p-mean)^2 formulation)
        float c, ssq = 0.0f, sab = 0.0f;
        c = p0 - mean; ssq += c*c; sab += fabsf(c);
        c = p1 - mean; ssq += c*c; sab += fabsf(c);
        c = p2 - mean; ssq += c*c; sab += fabsf(c);
        c = p3 - mean; ssq += c*c; sab += fabsf(c);
        c = p4 - mean; ssq += c*c; sab += fabsf(c);
        c = p5 - mean; ssq += c*c; sab += fabsf(c);
        c = p6 - mean; ssq += c*c; sab += fabsf(c);
        c = p7 - mean; ssq += c*c; sab += fabsf(c);
        c = p8 - mean; ssq += c*c; sab += fabsf(c);

        const float varu     = ssq * 0.125f;                       // /(K-1)
        const float contrast = (ssq * INV9) / fmaxf(varu, 1e-6f);  // popvar / std^2
        const float energy   = P2 * INV9;
        const float entropy  = -G * INV9;
        const float homog    = 1.0f / (1.0f + sab * INV9 + 1e-6f);

        // martingale: M = clamp(max(f,1e-5)*e^-0.5, 1e-4, 1e4)
        const float m0 = fminf(fmaxf(fmaxf(contrast, 1e-5f) * EMH, 1e-4f), 1e4f);
        const float m1 = fminf(fmaxf(fmaxf(energy,   1e-5f) * EMH, 1e-4f), 1e4f);
        const float m2 = fminf(fmaxf(fmaxf(entropy,  1e-5f) * EMH, 1e-4f), 1e4f);
        const float m3 = fminf(fmaxf(fmaxf(homog,    1e-5f) * EMH, 1e-4f), 1e4f);

        const int gh  = rowBase + lr;
        const int pix = gh * W + tx;
        outp[0 * (H * W) + pix] = m0;
        outp[1 * (H * W) + pix] = m1;
        outp[2 * (H * W) + pix] = m2;
        outp[3 * (H * W) + pix] = m3;
    }
}

extern "C" void kernel_launch(void* const* d_in, const int* in_sizes, int n_in,
                              void* d_out, int out_size) {
    const float* x = (const float*)d_in[0];
    float* out = (float*)d_out;
    dim3 block(128, 4);
    dim3 grid(H / TILE_H, BATCH * CIN);   // (8, 512)
    medseg_kernel<<<grid, block>>>(x, out);
}

// round 2
// speedup vs baseline: 1.3351x; 1.3351x over previous
#include <cuda_runtime.h>

// MedSegNet texture features, algebraically folded (theta=1):
//   g        = cl*ln(cl), cl = max(p,1e-6)  (precomputed once per input cell)
//   S,P2,G   = 3x3 box sums of p, p^2, g  via shared column sums
//   ssq      = P2 - S*mean   (== sum (p-mean)^2)
//   contrast = 8/9 unless var clamp active (ssq < 8e-6)
//   M(f)     = fmaxf(f * exp(-0.5), 1e-4)   for all features (all f>=0, f<<1e4)

#define H 128
#define W 128
#define NPLANES 512        // B*C = 8*64
#define TILE_H 16
#define SH (TILE_H + 2)
#define SW2 132            // padded row stride (floats); 16B-aligned rows

__global__ __launch_bounds__(256)
void medseg_kernel(const float* __restrict__ x, float* __restrict__ out) {
    const int bc = blockIdx.y;                 // plane in [0, 512)
    const int rowBase = blockIdx.x * TILE_H;   // row tile

    __shared__ __align__(16) float sp[SH][SW2];
    __shared__ __align__(16) float sg[SH][SW2];

    const int tx = threadIdx.x;                // 0..31 -> cols 4tx..4tx+3
    const int ty = threadIdx.y;                // 0..7
    const int tid = ty * 32 + tx;

    const float* __restrict__ plane = x + (size_t)bc * (H * W);

    // ---- fill tile+halo; shared col s = global col + 1 ----
    #pragma unroll 2
    for (int i = tid; i < SH * 130; i += 256) {
        const int sr = i / 130;
        const int sc = i - sr * 130;
        const int gr = rowBase + sr - 1;
        const int gc = sc - 1;
        float p = 0.0f;
        if ((unsigned)gr < (unsigned)H && (unsigned)gc < (unsigned)W)
            p = plane[gr * W + gc];
        const float cl = fmaxf(p, 1e-6f);
        sp[sr][sc] = p;
        sg[sr][sc] = cl * __logf(cl);          // pad cell -> 1e-6*ln(1e-6)
    }
    __syncthreads();

    const float INV9 = 1.0f / 9.0f;
    const float EMH  = 0.60653066f;            // exp(-0.5)
    float* __restrict__ outp = out + (size_t)(4 * bc) * (H * W);

    #pragma unroll
    for (int rr = 0; rr < 2; rr++) {
        const int lr = ty + rr * 8;            // local output row
        const int sr = lr + 1;
        const int sc = 4 * tx;                 // shared col of (global col 4tx - 1)

        // 3x6 register block of p and g (aligned LDS.128 + LDS.64)
        float p[3][6], g[3][6];
        #pragma unroll
        for (int r = 0; r < 3; r++) {
            const float4 a = *(const float4*)&sp[sr - 1 + r][sc];
            const float2 b = *(const float2*)&sp[sr - 1 + r][sc + 4];
            p[r][0]=a.x; p[r][1]=a.y; p[r][2]=a.z; p[r][3]=a.w; p[r][4]=b.x; p[r][5]=b.y;
            const float4 c = *(const float4*)&sg[sr - 1 + r][sc];
            const float2 d = *(const float2*)&sg[sr - 1 + r][sc + 4];
            g[r][0]=c.x; g[r][1]=c.y; g[r][2]=c.z; g[r][3]=c.w; g[r][4]=d.x; g[r][5]=d.y;
        }

        // column sums shared by the 4 output pixels
        float cp[6], cq[6], cg[6];
        #pragma unroll
        for (int j = 0; j < 6; j++) {
            cp[j] = p[0][j] + p[1][j] + p[2][j];
            cq[j] = fmaf(p[0][j], p[0][j], fmaf(p[1][j], p[1][j], p[2][j] * p[2][j]));
            cg[j] = g[0][j] + g[1][j] + g[2][j];
        }

        float m0v[4], m1v[4], m2v[4], m3v[4];
        #pragma unroll
        for (int i = 0; i < 4; i++) {
            const float S  = cp[i] + cp[i+1] + cp[i+2];
            const float P2 = cq[i] + cq[i+1] + cq[i+2];
            const float G  = cg[i] + cg[i+1] + cg[i+2];
            const float mean = S * INV9;
            const float ssq  = fmaf(-S, mean, P2);      // sum (p-mean)^2

            float sab = 0.0f;                            // sum |p-mean|
            #pragma unroll
            for (int r = 0; r < 3; r++) {
                sab += fabsf(p[r][i]     - mean);
                sab += fabsf(p[r][i + 1] - mean);
                sab += fabsf(p[r][i + 2] - mean);
            }

            // contrast: (ssq/9)/max(ssq/8,1e-6) -> 8/9 unless clamp branch
            m0v[i] = (ssq >= 8e-6f) ? 0.53913838f                 // (8/9)*e^-.5
                                    : fmaxf(ssq * 67392.295f, 1e-4f); // (1e6/9)*e^-.5
            m1v[i] = fmaxf(P2 *  0.067392295f, 1e-4f);   // energy*e^-.5
            m2v[i] = fmaxf(G  * -0.067392295f, 1e-4f);   // entropy*e^-.5 (G<=0)
            const float t = fmaf(sab, INV9, 1.000001f);
            m3v[i] = fmaxf(__fdividef(EMH, t), 1e-4f);   // homogeneity*e^-.5
        }

        float* op = outp + (rowBase + lr) * W + 4 * tx;
        *(float4*)(op)             = make_float4(m0v[0], m0v[1], m0v[2], m0v[3]);
        *(float4*)(op + H * W)     = make_float4(m1v[0], m1v[1], m1v[2], m1v[3]);
        *(float4*)(op + 2 * H * W) = make_float4(m2v[0], m2v[1], m2v[2], m2v[3]);
        *(float4*)(op + 3 * H * W) = make_float4(m3v[0], m3v[1], m3v[2], m3v[3]);
    }
}

extern "C" void kernel_launch(void* const* d_in, const int* in_sizes, int n_in,
                              void* d_out, int out_size) {
    const float* x = (const float*)d_in[0];
    float* out = (float*)d_out;
    dim3 block(32, 8);
    dim3 grid(H / TILE_H, NPLANES);   // (8, 512)
    medseg_kernel<<<grid, block>>>(x, out);
}

// round 3
// speedup vs baseline: 1.5563x; 1.1656x over previous
#include <cuda_runtime.h>

// MedSegNet texture features, algebraically folded (theta=1):
//   g        = cl*ln(cl), cl = max(p,1e-6)  (precomputed once per input cell)
//   S,P2,G   = 3x3 box sums of p, p^2, g  via per-thread column sums
//   ssq      = P2 - S*mean   (== sum (p-mean)^2)
//   contrast*e^-.5 = min(max(ssq*67392.295, 1e-4), 8/9*e^-.5)   (branchless clamp fold)
//   M(f)     = fmaxf(f * exp(-0.5), 1e-4)   (all f >= 0, f << 1e4)

#define H 128
#define W 128
#define NPLANES 512        // B*C = 8*64
#define TILE_H 16
#define SH (TILE_H + 2)
#define SW2 132            // padded row stride (16B-aligned rows)
#define GPAD (-1.3815511e-5f)   // 1e-6 * ln(1e-6): g of a zero-pad cell

__global__ __launch_bounds__(256)
void medseg_kernel(const float* __restrict__ x, float* __restrict__ out) {
    const int bc = blockIdx.y;                 // plane in [0, 512)
    const int rowBase = blockIdx.x * TILE_H;   // row tile

    __shared__ __align__(16) float sp[SH][SW2];
    __shared__ __align__(16) float sg[SH][SW2];

    const int tx = threadIdx.x;                // 0..31
    const int ty = threadIdx.y;                // 0..7

    const float* __restrict__ plane = x + (size_t)bc * (H * W);

    // ---- load phase: warp ty fills shared rows ty, ty+8, ty+16 ----
    // Warp-uniform row branch; coalesced LDG; conflict-free scalar STS.
    #pragma unroll
    for (int rep = 0; rep < 3; rep++) {
        const int sr = ty + rep * 8;
        if (sr < SH) {
            const int gr = rowBase + sr - 1;
            if ((unsigned)gr < (unsigned)H) {
                const float* __restrict__ rp = plane + gr * W;
                #pragma unroll
                for (int k = 0; k < 4; k++) {
                    const float p = rp[tx + 32 * k];
                    const float cl = fmaxf(p, 1e-6f);
                    sp[sr][tx + 32 * k + 1] = p;
                    sg[sr][tx + 32 * k + 1] = cl * __logf(cl);
                }
            } else {
                #pragma unroll
                for (int k = 0; k < 4; k++) {
                    sp[sr][tx + 32 * k + 1] = 0.0f;
                    sg[sr][tx + 32 * k + 1] = GPAD;
                }
            }
            if (tx == 0) {                      // halo columns (gc=-1, gc=128)
                sp[sr][0]   = 0.0f;  sg[sr][0]   = GPAD;
                sp[sr][129] = 0.0f;  sg[sr][129] = GPAD;
            }
        }
    }
    __syncthreads();

    const float INV9 = 1.0f / 9.0f;
    const float EMH  = 0.60653066f;            // exp(-0.5)
    const float C89E = 0.53913838f;            // (8/9)*exp(-0.5)
    const float CCLP = 67392.295f;             // (1e6/9)*exp(-0.5)
    const float CE9  = 0.067392295f;           // exp(-0.5)/9

    float* __restrict__ outp = out + (size_t)(4 * bc) * (H * W);

    #pragma unroll
    for (int rr = 0; rr < 2; rr++) {
        const int lr = ty + rr * 8;            // local output row
        const int sr = lr + 1;
        const int sc = 4 * tx;                 // shared col of (global col 4tx - 1)

        // 3x6 register block of p and g (aligned LDS.128 + LDS.64)
        float p[3][6], g[3][6];
        #pragma unroll
        for (int r = 0; r < 3; r++) {
            const float4 a = *(const float4*)&sp[sr - 1 + r][sc];
            const float2 b = *(const float2*)&sp[sr - 1 + r][sc + 4];
            p[r][0]=a.x; p[r][1]=a.y; p[r][2]=a.z; p[r][3]=a.w; p[r][4]=b.x; p[r][5]=b.y;
            const float4 c = *(const float4*)&sg[sr - 1 + r][sc];
            const float2 d = *(const float2*)&sg[sr - 1 + r][sc + 4];
            g[r][0]=c.x; g[r][1]=c.y; g[r][2]=c.z; g[r][3]=c.w; g[r][4]=d.x; g[r][5]=d.y;
        }

        // column sums shared by the 4 output pixels
        float cp[6], cq[6], cg[6];
        #pragma unroll
        for (int j = 0; j < 6; j++) {
            cp[j] = p[0][j] + p[1][j] + p[2][j];
            cq[j] = fmaf(p[0][j], p[0][j], fmaf(p[1][j], p[1][j], p[2][j] * p[2][j]));
            cg[j] = g[0][j] + g[1][j] + g[2][j];
        }

        float m0v[4], m1v[4], m2v[4], m3v[4];
        #pragma unroll
        for (int i = 0; i < 4; i++) {
            const float S  = cp[i] + cp[i+1] + cp[i+2];
            const float P2 = cq[i] + cq[i+1] + cq[i+2];
            const float G  = cg[i] + cg[i+1] + cg[i+2];
            const float mean = S * INV9;
            const float ssq  = fmaf(-S, mean, P2);      // sum (p-mean)^2

            float sab = 0.0f;                            // sum |p-mean|
            #pragma unroll
            for (int r = 0; r < 3; r++) {
                sab += fabsf(p[r][i]     - mean);
                sab += fabsf(p[r][i + 1] - mean);
                sab += fabsf(p[r][i + 2] - mean);
            }

            m0v[i] = fminf(fmaxf(ssq * CCLP, 1e-4f), C89E);  // contrast (branchless)
            m1v[i] = fmaxf(P2 *  CE9, 1e-4f);                // energy
            m2v[i] = fmaxf(G  * -CE9, 1e-4f);                // entropy (G<=0)
            const float t = fmaf(sab, INV9, 1.000001f);
            m3v[i] = fmaxf(__fdividef(EMH, t), 1e-4f);       // homogeneity
        }

        float* op = outp + (rowBase + lr) * W + 4 * tx;
        *(float4*)(op)             = make_float4(m0v[0], m0v[1], m0v[2], m0v[3]);
        *(float4*)(op + H * W)     = make_float4(m1v[0], m1v[1], m1v[2], m1v[3]);
        *(float4*)(op + 2 * H * W) = make_float4(m2v[0], m2v[1], m2v[2], m2v[3]);
        *(float4*)(op + 3 * H * W) = make_float4(m3v[0], m3v[1], m3v[2], m3v[3]);
    }
}

extern "C" void kernel_launch(void* const* d_in, const int* in_sizes, int n_in,
                              void* d_out, int out_size) {
    const float* x = (const float*)d_in[0];
    float* out = (float*)d_out;
    dim3 block(32, 8);
    dim3 grid(H / TILE_H, NPLANES);   // (8, 512)
    medseg_kernel<<<grid, block>>>(x, out);
}